// round 15
// baseline (speedup 1.0000x reference)
#include <cuda_runtime.h>
#include <cuda_bf16.h>
#include <math.h>
#include <stdint.h>

#define TT   512
#define BB   64
#define DD   1024
#define NBK  16
#define TOKN (TT*BB)                 // 32768
#define CAP  8192
#define NLIST (NBK*CAP)
#define OUT_OFF ((size_t)TOKN*64)
#define NKTI (DD/16)                 // 64 k-stages of 16

// ---------------- scratch ---------------------------------------------------
__device__ float    g_q[(size_t)TOKN*64];
__device__ float    g_w[TOKN*NBK];
__device__ int      g_sel[TOKN*2];
// per (token,slot) entry: 64 rows x (k, v, beta_pre, pad)  -> one LDG.128/row
__device__ float    g_selout[(size_t)TOKN*2*256];    // 64 MB
__device__ float    g_partial[(size_t)TOKN*NBK*64];  // 134 MB
__device__ unsigned g_list[NLIST];
__device__ int      g_cursor[NBK];
// W prepack (12.6 MB): unit (row R, kti, j) = (h_b0, h_b1, l_b0, l_b1)
__device__ uint4    g_wpack[(size_t)NBK*192*256];
// rq W prepack: [kti 64][unit 640] ; unit (nt,s,lane) = (h_r0,h_r1,l_r0,l_r1)
__device__ uint4    g_rqpack[64*640];                // 640 KB

// ---------------- fast math --------------------------------------------------
__device__ __forceinline__ float ex2a(float x){ float r; asm("ex2.approx.f32 %0,%1;":"=f"(r):"f"(x)); return r; }
__device__ __forceinline__ float rcpa(float x){ float r; asm("rcp.approx.f32 %0,%1;":"=f"(r):"f"(x)); return r; }
__device__ __forceinline__ float fast_rcp(float z){ float y = rcpa(z); return y * fmaf(-z, y, 2.0f); }
__device__ __forceinline__ float fsig(float x){ float E = ex2a(-1.44269504f * x); return fast_rcp(1.0f + E); }
__device__ __forceinline__ float ftanh(float x){ float E = ex2a(2.88539008f * x); return fmaf(-2.0f, fast_rcp(1.0f + E), 1.0f); }

__device__ __forceinline__ uint32_t f2tf(float f){ uint32_t r; asm("cvt.rna.tf32.f32 %0,%1;":"=r"(r):"f"(f)); return r; }
__device__ __forceinline__ uint32_t bf16r(float f){ uint16_t r; asm("cvt.rn.bf16.f32 %0,%1;":"=h"(r):"f"(f)); return (uint32_t)r; }
__device__ __forceinline__ void split_pack(float a, float b, uint32_t &hi, uint32_t &lo){
    uint32_t ha = bf16r(a), hb = bf16r(b);
    float ra = a - __uint_as_float(ha << 16);
    float rb = b - __uint_as_float(hb << 16);
    hi = ha | (hb << 16);
    lo = bf16r(ra) | (bf16r(rb) << 16);
}

__device__ __forceinline__ void mma_tf32(float4 &d, const uint4 &a, const uint2 &b){
    asm volatile("mma.sync.aligned.m16n8k8.row.col.f32.tf32.tf32.f32 "
                 "{%0,%1,%2,%3},{%4,%5,%6,%7},{%8,%9},{%0,%1,%2,%3};"
                 : "+f"(d.x), "+f"(d.y), "+f"(d.z), "+f"(d.w)
                 : "r"(a.x), "r"(a.y), "r"(a.z), "r"(a.w), "r"(b.x), "r"(b.y));
}
__device__ __forceinline__ void mma_bf16(float4 &d, uint32_t a0, uint32_t a1, uint32_t a2, uint32_t a3,
                                         uint32_t b0, uint32_t b1){
    asm volatile("mma.sync.aligned.m16n8k16.row.col.f32.bf16.bf16.f32 "
                 "{%0,%1,%2,%3},{%4,%5,%6,%7},{%8,%9},{%0,%1,%2,%3};"
                 : "+f"(d.x), "+f"(d.y), "+f"(d.z), "+f"(d.w)
                 : "r"(a0), "r"(a1), "r"(a2), "r"(a3), "r"(b0), "r"(b1));
}

__device__ __forceinline__ void cpa16(uint32_t dst, const void* src){
    asm volatile("cp.async.cg.shared.global [%0], [%1], 16;\n" :: "r"(dst), "l"(src));
}
__device__ __forceinline__ void cpa_commit(){ asm volatile("cp.async.commit_group;\n"); }
template<int N> __device__ __forceinline__ void cpa_wait(){ asm volatile("cp.async.wait_group %0;\n"::"n"(N)); }

// ---------------- K0: prep — W split-pack + rq prepack + list init -----------
__global__ __launch_bounds__(256) void k_prep(const float* __restrict__ Wkv,
                                              const float* __restrict__ Wbeta,
                                              const float* __restrict__ Wr,
                                              const float* __restrict__ Wq) {
    const int bid = blockIdx.x, tid = threadIdx.x;
    if (bid < NBK * 192) {
        const int kti = tid >> 2, j = tid & 3;
        int e = bid / 192, n = bid % 192;
        const float* base = (n < 128) ? (Wkv + ((size_t)e * 128 + n) * DD)
                                      : (Wbeta + ((size_t)e * 64 + (n - 128)) * DD);
        const float* src = base + kti * 16 + 2 * j;
        float2 v0 = *(const float2*)src;
        float2 v1 = *(const float2*)(src + 8);
        uint32_t h0, l0, h1, l1;
        split_pack(v0.x, v0.y, h0, l0);
        split_pack(v1.x, v1.y, h1, l1);
        g_wpack[(size_t)bid * 256 + tid] = make_uint4(h0, h1, l0, l1);
    } else if (bid < NBK * 192 + 64) {
        const int kti = bid - NBK * 192;
#pragma unroll
        for (int it = 0; it < 3; it++) {
            int u = tid + it * 256;
            if (u < 640) {
                int nt = u >> 6, rem = u & 63;
                int s = rem >> 5, lane = rem & 31;
                int n = nt * 8 + (lane >> 2);
                const float* wp = (n < 16) ? (Wr + (size_t)n * DD)
                                           : (Wq + (size_t)(n - 16) * DD);
                int k0 = kti * 16 + s * 8 + (lane & 3);
                float e0 = wp[k0], e1 = wp[k0 + 4];
                uint32_t h0 = f2tf(e0), h1 = f2tf(e1);
                uint32_t l0 = f2tf(e0 - __uint_as_float(h0));
                uint32_t l1 = f2tf(e1 - __uint_as_float(h1));
                g_rqpack[kti * 640 + u] = make_uint4(h0, h1, l0, l1);
            }
        }
    } else {
        int i = (bid - (NBK * 192 + 64)) * 256 + tid;
        if (i < NLIST) g_list[i] = 0xFFFFFFFFu;
        if (i < NBK)   g_cursor[i] = i * CAP;
    }
}

// ---------------- K1: router+q GEMM (tf32 3-split, cp.async W) + topk/fill ---
__global__ __launch_bounds__(256) void k_rq_mma(const float* __restrict__ x) {
    __shared__ uint32_t Ah[4*2*32*4], Al[4*2*32*4];
    __shared__ __align__(16) uint4 SB[2][640];     // 20 KB, double-buffered W
    __shared__ float slog[64][20];

    const int tid = threadIdx.x;
    const int row0 = blockIdx.x * 64;
    const int warp = tid >> 5, lane = tid & 31;
    const int wm = warp >> 1, wn = warp & 1;

    float4 acc[5];
#pragma unroll
    for (int j = 0; j < 5; j++) acc[j] = make_float4(0.f, 0.f, 0.f, 0.f);

    const int xrow = tid >> 2, xk0 = (tid & 3) * 4;
    const float* xp = x + (size_t)(row0 + xrow) * DD + xk0;
    const int xs = xk0 >> 3;
    const int xreg = ((xk0 & 4) ? 2 : 0) + (((xrow & 15) >= 8) ? 1 : 0);
    const int xbase = ((((xrow >> 4) * 2 + xs) * 32 + ((xrow & 7) << 2)) << 2) + xreg;

    const uint4* b_src[3];
    uint32_t b_dst[3];
#pragma unroll
    for (int i = 0; i < 3; i++) {
        int u = tid + i * 256;
        if (u < 640) {
            b_src[i] = &g_rqpack[u];
            b_dst[i] = (uint32_t)__cvta_generic_to_shared(&SB[0][u]);
        } else { b_src[i] = nullptr; b_dst[i] = 0; }
    }
    const uint32_t BBUF = 640 * sizeof(uint4);

#pragma unroll
    for (int i = 0; i < 3; i++) if (b_src[i]) cpa16(b_dst[i], b_src[i]);
    cpa_commit();

    for (int kts = 0; kts < NKTI; kts++) {
        const int buf = kts & 1;
        const int kt = kts * 16;
        {
            float4 v = *(const float4*)(xp + kt);
            float vv[4] = {v.x, v.y, v.z, v.w};
#pragma unroll
            for (int j = 0; j < 4; j++) {
                uint32_t h = f2tf(vv[j]);
                Ah[xbase + (j << 2)] = h;
                Al[xbase + (j << 2)] = f2tf(vv[j] - __uint_as_float(h));
            }
        }
        const bool more = (kts + 1 < NKTI);
        if (more) {
            uint32_t bo = (buf ^ 1) * BBUF;
#pragma unroll
            for (int i = 0; i < 3; i++)
                if (b_src[i]) cpa16(b_dst[i] + bo, b_src[i] + (size_t)(kts + 1) * 640);
            cpa_commit();
            cpa_wait<1>();
        } else {
            cpa_wait<0>();
        }
        __syncthreads();
#pragma unroll
        for (int s = 0; s < 2; s++) {
            int aidx = (((wm * 2 + s) * 32 + lane) << 2);
            uint4 ah = *(const uint4*)&Ah[aidx];
            uint4 al = *(const uint4*)&Al[aidx];
#pragma unroll
            for (int ni = 0; ni < 5; ni++) {
                uint4 qb = SB[buf][((wn * 5 + ni) * 2 + s) * 32 + lane];
                uint2 bh = make_uint2(qb.x, qb.y);
                uint2 bl = make_uint2(qb.z, qb.w);
                mma_tf32(acc[ni], ah, bh);
                mma_tf32(acc[ni], ah, bl);
                mma_tf32(acc[ni], al, bh);
            }
        }
        __syncthreads();
    }
    int rloc = wm * 16 + (lane >> 2);
    int r0 = row0 + rloc;
#pragma unroll
    for (int ni = 0; ni < 5; ni++) {
        int c0 = wn * 40 + ni * 8 + ((lane & 3) << 1);
        if (c0 < 16) {
            slog[rloc][c0]     = acc[ni].x; slog[rloc][c0 + 1]     = acc[ni].y;
            slog[rloc + 8][c0] = acc[ni].z; slog[rloc + 8][c0 + 1] = acc[ni].w;
        } else {
            int c = c0 - 16;
            *(float2*)&g_q[(size_t)r0 * 64 + c]       = make_float2(acc[ni].x, acc[ni].y);
            *(float2*)&g_q[(size_t)(r0 + 8) * 64 + c] = make_float2(acc[ni].z, acc[ni].w);
        }
    }
    __syncthreads();
    if (tid < 64) {
        int tok = row0 + tid;
        float lg[16];
#pragma unroll
        for (int c = 0; c < 16; c++) lg[c] = slog[tid][c];
        float v0 = -1e30f, v1 = -1e30f; int i0 = 0, i1 = 0;
#pragma unroll
        for (int c = 0; c < 16; c++) {
            float l = lg[c];
            if (l > v0) { v1 = v0; i1 = i0; v0 = l; i0 = c; }
            else if (l > v1) { v1 = l; i1 = c; }
        }
        float s = 0.0f, w[16];
#pragma unroll
        for (int c = 0; c < 16; c++) { float e = __expf(lg[c] - v0); w[c] = e; s += e; }
        float rs = 1.0f / s;
#pragma unroll
        for (int c = 0; c < 16; c++) g_w[(size_t)tok * 16 + c] = w[c] * rs;
        g_sel[tok * 2 + 0] = i0;
        g_sel[tok * 2 + 1] = i1;
        int p0 = atomicAdd(&g_cursor[i0], 1); g_list[p0] = (unsigned)(tok * 2);
        int p1 = atomicAdd(&g_cursor[i1], 1); g_list[p1] = (unsigned)(tok * 2 + 1);
    }
}

// ---------------- K2: grouped bf16 3-split GEMM (unchanged) ------------------
__global__ __launch_bounds__(256, 2) void k_ggemm(const float* __restrict__ x) {
    __shared__ __align__(16) uint4 SMA[2][4 * 2 * 32];
    __shared__ __align__(16) uint4 SMB[2][24 * 32];
    __shared__ unsigned s_ent[64];

    const int tid = threadIdx.x;
    const int e = blockIdx.x >> 7;
    const int lofs = e * CAP + (blockIdx.x & 127) * 64;
    if (tid < 64) s_ent[tid] = g_list[lofs + tid];
    __syncthreads();
    if (s_ent[0] == 0xFFFFFFFFu) return;

    const int warp = tid >> 5, lane = tid & 31;
    const int wm = warp >> 2, wn = warp & 3;

    const int a_mt = tid >> 6, a_rlow = (tid >> 3) & 7, a_j = tid & 7;
    const int a_lane = a_rlow * 4 + (a_j & 3);
    const int a_reg  = (a_j >= 4) ? 2 : 0;
    const float* a_p0;
    const float* a_p1;
    {
        unsigned e0 = s_ent[a_mt * 16 + a_rlow];
        unsigned e1 = s_ent[a_mt * 16 + a_rlow + 8];
        a_p0 = (e0 != 0xFFFFFFFFu) ? (x + (size_t)(e0 >> 1) * DD + 2 * a_j) : nullptr;
        a_p1 = (e1 != 0xFFFFFFFFu) ? (x + (size_t)(e1 >> 1) * DD + 2 * a_j) : nullptr;
    }
    uint32_t a_hi_addr = (uint32_t)__cvta_generic_to_shared(
        &((uint32_t*)&SMA[0][(a_mt * 2 + 0) * 32 + a_lane])[a_reg]);
    uint32_t a_lo_addr = (uint32_t)__cvta_generic_to_shared(
        &((uint32_t*)&SMA[0][(a_mt * 2 + 1) * 32 + a_lane])[a_reg]);

    const uint4* b_src[3];
    uint32_t b_dst[3];
#pragma unroll
    for (int i = 0; i < 3; i++) {
        int u = tid + i * 256;
        int n = u >> 2, j = u & 3;
        b_src[i] = &g_wpack[((size_t)e * 192 + n) * 256 + j];
        b_dst[i] = (uint32_t)__cvta_generic_to_shared(&SMB[0][(n >> 3) * 32 + (n & 7) * 4 + j]);
    }

    float4 acc[2][6];
#pragma unroll
    for (int i = 0; i < 2; i++)
#pragma unroll
        for (int j = 0; j < 6; j++) acc[i][j] = make_float4(0.f, 0.f, 0.f, 0.f);

    {
        float2 v0 = make_float2(0.f, 0.f), v1 = v0;
        if (a_p0) v0 = *(const float2*)a_p0;
        if (a_p1) v1 = *(const float2*)a_p1;
        uint32_t h0, l0, h1, l1;
        split_pack(v0.x, v0.y, h0, l0);
        split_pack(v1.x, v1.y, h1, l1);
        asm volatile("st.shared.v2.u32 [%0], {%1,%2};" :: "r"(a_hi_addr), "r"(h0), "r"(h1));
        asm volatile("st.shared.v2.u32 [%0], {%1,%2};" :: "r"(a_lo_addr), "r"(l0), "r"(l1));
#pragma unroll
        for (int i = 0; i < 3; i++) cpa16(b_dst[i], b_src[i]);
        cpa_commit();
    }

    const uint32_t ABUF = sizeof(uint4) * 4 * 2 * 32;
    const uint32_t BBUF = sizeof(uint4) * 24 * 32;

    for (int kts = 0; kts < NKTI; kts++) {
        const int buf = kts & 1;
        float2 va0 = make_float2(0.f, 0.f), va1 = va0;
        const bool more = (kts + 1 < NKTI);
        if (more) {
            if (a_p0) va0 = *(const float2*)(a_p0 + (kts + 1) * 16);
            if (a_p1) va1 = *(const float2*)(a_p1 + (kts + 1) * 16);
        }
        cpa_wait<0>();
        __syncthreads();
        if (more) {
            uint32_t bo = (buf ^ 1) * BBUF;
#pragma unroll
            for (int i = 0; i < 3; i++) cpa16(b_dst[i] + bo, b_src[i] + (size_t)(kts + 1) * 4);
            cpa_commit();
        }
        {
            const uint4* A0 = SMA[buf];
            const uint4* B0 = SMB[buf];
            uint4 qa_h[2], qa_l[2];
#pragma unroll
            for (int mi = 0; mi < 2; mi++) {
                int mt = wm * 2 + mi;
                qa_h[mi] = A0[(mt * 2 + 0) * 32 + lane];
                qa_l[mi] = A0[(mt * 2 + 1) * 32 + lane];
            }
#pragma unroll
            for (int ni = 0; ni < 6; ni++) {
                uint4 qb = B0[(wn * 6 + ni) * 32 + lane];
#pragma unroll
                for (int mi = 0; mi < 2; mi++) {
                    float4 &d = acc[mi][ni];
                    mma_bf16(d, qa_h[mi].x, qa_h[mi].y, qa_h[mi].z, qa_h[mi].w, qb.x, qb.y);
                    mma_bf16(d, qa_h[mi].x, qa_h[mi].y, qa_h[mi].z, qa_h[mi].w, qb.z, qb.w);
                    mma_bf16(d, qa_l[mi].x, qa_l[mi].y, qa_l[mi].z, qa_l[mi].w, qb.x, qb.y);
                }
            }
        }
        if (more) {
            uint32_t h0, l0, h1, l1;
            split_pack(va0.x, va0.y, h0, l0);
            split_pack(va1.x, va1.y, h1, l1);
            uint32_t ao = (buf ^ 1) * ABUF;
            asm volatile("st.shared.v2.u32 [%0], {%1,%2};" :: "r"(a_hi_addr + ao), "r"(h0), "r"(h1));
            asm volatile("st.shared.v2.u32 [%0], {%1,%2};" :: "r"(a_lo_addr + ao), "r"(l0), "r"(l1));
        }
    }

    // epilogue: scatter into interleaved (k,v,bp,pad) layout
#pragma unroll
    for (int mi = 0; mi < 2; mi++) {
        int r0 = (wm * 2 + mi) * 16 + (lane >> 2);
        unsigned e0 = s_ent[r0], e1 = s_ent[r0 + 8];
#pragma unroll
        for (int ni = 0; ni < 6; ni++) {
            int c0 = wn * 48 + ni * 8 + ((lane & 3) << 1);
            float va[2] = {acc[mi][ni].x, acc[mi][ni].y};
            float vb[2] = {acc[mi][ni].z, acc[mi][ni].w};
#pragma unroll
            for (int j = 0; j < 2; j++) {
                int cc = c0 + j;
                int ofs = ((cc & 63) << 2) + (cc >> 6);
                if (e0 != 0xFFFFFFFFu) g_selout[(size_t)e0 * 256 + ofs] = va[j];
                if (e1 != 0xFFFFFFFFu) g_selout[(size_t)e1 * 256 + ofs] = vb[j];
            }
        }
    }
}

// ---------------- K3: recurrent scan v7 — split rows, 128 thr/CTA ------------
// thread (h = tid>>6, i = tid&63) owns S[i][ 32h .. 32h+32 ); 4096 warps total.
__global__ __launch_bounds__(128, 8) void k_scan(const float* __restrict__ b_beta,
                                                 float* __restrict__ out) {
    const int bc = blockIdx.x;
    const int b = bc >> 4, c = bc & 15;
    const int tid = threadIdx.x;
    const int i = tid & 63;          // row
    const int h = tid >> 6;          // column half
    const int j0 = h * 8;            // first float4 column index

    float4 S[8];
#pragma unroll
    for (int j = 0; j < 8; j++) S[j] = make_float4(0.f, 0.f, 0.f, 0.f);
    const float bb = b_beta[c * 64 + i];

    __shared__ __align__(16) float sq[2][64];
    __shared__ __align__(16) float sk[2][64];
    __shared__ float sredA[2][64];   // retr partials (selected steps)
    __shared__ float snorm[2];       // k^2 partials per half
    __shared__ float sredB[2][64];   // Sq partials (every step)

    // marching pointers
    const float*  qp   = g_q + (size_t)b * 64 + i;
    const int2*   selp = (const int2*)g_sel + b;
    const float*  wp   = g_w + (size_t)b * 16 + c;
    const float*  sop  = g_selout + (size_t)b * 512 + i * 4;
    float*        pp   = g_partial + ((size_t)b * 16 + c) * 64 + i;

    // prefetch t = 0 (independent loads; both slots)
    float qv = *qp;
    int2  sel = *selp;
    float wv = *wp;
    float4 f0 = *(const float4*)sop;
    float4 f1 = *(const float4*)(sop + 256);

    for (int t = 0; t < TT; t++) {
        const int p = t & 1;
        const int slotc = (sel.x == c) ? 0 : ((sel.y == c) ? 1 : -1);
        float4 fc = (slotc == 1) ? f1 : f0;   // (k[i], v[i], bp[i], pad)
        const float wvc = wv;
        if (h == 0) { sq[p][i] = qv; sk[p][i] = fc.x; }
        __syncthreads();                      // bar1: sq/sk visible

        // prefetch t+1
        if (t + 1 < TT) {
            qp += BB * 64; selp += BB; wp += BB * 16; sop += (size_t)BB * 512;
            qv = *qp;
            sel = *selp;
            wv = *wp;
            f0 = *(const float4*)sop;
            f1 = *(const float4*)(sop + 256);
        }

        if (slotc >= 0) {                     // CTA-uniform
            const float4* k4 = (const float4*)sk[p] + j0;
            float r0 = 0.f, r1 = 0.f, n0 = 0.f, n1 = 0.f;
#pragma unroll
            for (int j = 0; j < 8; j++) {
                float4 kq = k4[j];
                r0 = fmaf(S[j].x, kq.x, r0); n0 = fmaf(kq.x, kq.x, n0);
                r1 = fmaf(S[j].y, kq.y, r1); n1 = fmaf(kq.y, kq.y, n1);
                r0 = fmaf(S[j].z, kq.z, r0); n0 = fmaf(kq.z, kq.z, n0);
                r1 = fmaf(S[j].w, kq.w, r1); n1 = fmaf(kq.w, kq.w, n1);
            }
            sredA[h][i] = r0 + r1;
            if (i == 0) snorm[h] = n0 + n1;
            __syncthreads();                  // bar2: partials visible
            float retr_raw = sredA[0][i] + sredA[1][i];
            float ps = snorm[0] + snorm[1];
            float rn = fast_rcp(sqrtf(ps) + 1e-6f);
            float delta = fc.y - retr_raw * rn;
            float beta = fsig(fc.z + bb);
            float sc = delta * rn;
#pragma unroll
            for (int j = 0; j < 8; j++) {
                float4 kq = k4[j];
                S[j].x = ftanh(fmaf(beta, S[j].x, sc * kq.x));
                S[j].y = ftanh(fmaf(beta, S[j].y, sc * kq.y));
                S[j].z = ftanh(fmaf(beta, S[j].z, sc * kq.z));
                S[j].w = ftanh(fmaf(beta, S[j].w, sc * kq.w));
            }
        }
        const float4* q4 = (const float4*)sq[p] + j0;
        float a0 = 0.f, a1 = 0.f;
#pragma unroll
        for (int j = 0; j < 8; j++) {
            float4 qq = q4[j];
            a0 = fmaf(S[j].x, qq.x, a0);
            a1 = fmaf(S[j].y, qq.y, a1);
            a0 = fmaf(S[j].z, qq.z, a0);
            a1 = fmaf(S[j].w, qq.w, a1);
        }
        sredB[h][i] = a0 + a1;
        __syncthreads();                      // bar3: Sq partials visible
        if (h == 0) {
            float sv = sredB[0][i] + sredB[1][i];
            *pp = wvc * sv * sv * fsig(sv);
        }
        pp += (size_t)BB * NBK * 64;
    }
    float* Sf = out + OUT_OFF;
    size_t base = (((size_t)b * 16 + c) * 64 + i) * 64 + h * 32;
#pragma unroll
    for (int j = 0; j < 8; j++) *(float4*)&Sf[base + j * 4] = S[j];
}

// ---------------- K4: reduce over blocks -> outputs (float4) -----------------
__global__ void k_reduce(float* __restrict__ out) {
    int idx = blockIdx.x * 256 + threadIdx.x;      // over TOKN*16 float4s
    int tok = idx >> 4, i4 = idx & 15;
    const float4* p = (const float4*)(g_partial + (size_t)tok * 1024) + i4;
    float4 s = make_float4(0.f, 0.f, 0.f, 0.f);
#pragma unroll
    for (int c = 0; c < 16; c++) {
        float4 v = p[c * 16];
        s.x += v.x; s.y += v.y; s.z += v.z; s.w += v.w;
    }
    ((float4*)out)[idx] = s;
}

// ---------------- launch -----------------------------------------------------
extern "C" void kernel_launch(void* const* d_in, const int* in_sizes, int n_in,
                              void* d_out, int out_size) {
    const float* x    = (const float*)d_in[0];
    const float* Wr   = (const float*)d_in[1];
    const float* Wkv  = (const float*)d_in[2];
    const float* Wb   = (const float*)d_in[3];
    const float* bb   = (const float*)d_in[4];
    const float* Wq   = (const float*)d_in[5];
    float* out = (float*)d_out;
    (void)in_sizes; (void)n_in; (void)out_size;

    const int prep_grid = NBK * 192 + 64 + (NLIST + 255) / 256;   // 3648
    k_prep<<<prep_grid, 256>>>(Wkv, Wb, Wr, Wq);
    k_rq_mma<<<TOKN / 64, 256>>>(x);
    k_ggemm<<<NBK * (CAP / 64), 256>>>(x);
    k_scan<<<BB * NBK, 128>>>(bb, out);
    k_reduce<<<(TOKN * 16) / 256, 256>>>(out);
}

// round 17
// speedup vs baseline: 1.0412x; 1.0412x over previous
#include <cuda_runtime.h>
#include <cuda_bf16.h>
#include <math.h>
#include <stdint.h>

#define TT   512
#define BB   64
#define DD   1024
#define NBK  16
#define TOKN (TT*BB)                 // 32768
#define CAP  8192
#define NLIST (NBK*CAP)
#define OUT_OFF ((size_t)TOKN*64)
#define NKTI (DD/16)                 // 64 k-stages of 16

// ---------------- scratch ---------------------------------------------------
__device__ float    g_q[(size_t)TOKN*64];
__device__ float    g_w[TOKN*NBK];
__device__ int      g_sel[TOKN*2];
// per (token,slot) entry: 64 rows x (k, v, beta_pre, pad)  -> one LDG.128/row
__device__ float    g_selout[(size_t)TOKN*2*256];    // 64 MB
__device__ float    g_partial[(size_t)TOKN*NBK*64];  // 134 MB
__device__ unsigned g_list[NLIST];
__device__ int      g_cursor[NBK];
// W prepack (12.6 MB): unit (row R, kti, j) = (h_b0, h_b1, l_b0, l_b1)
__device__ uint4    g_wpack[(size_t)NBK*192*256];
// rq W prepack: [kti 64][unit 640] ; unit (nt,s,lane) = (h_r0,h_r1,l_r0,l_r1)
__device__ uint4    g_rqpack[64*640];                // 640 KB

// ---------------- fast math --------------------------------------------------
__device__ __forceinline__ float ex2a(float x){ float r; asm("ex2.approx.f32 %0,%1;":"=f"(r):"f"(x)); return r; }
__device__ __forceinline__ float rcpa(float x){ float r; asm("rcp.approx.f32 %0,%1;":"=f"(r):"f"(x)); return r; }
__device__ __forceinline__ float fast_rcp(float z){ float y = rcpa(z); return y * fmaf(-z, y, 2.0f); }
__device__ __forceinline__ float fsig(float x){ float E = ex2a(-1.44269504f * x); return fast_rcp(1.0f + E); }
__device__ __forceinline__ float ftanh(float x){ float E = ex2a(2.88539008f * x); return fmaf(-2.0f, fast_rcp(1.0f + E), 1.0f); }

__device__ __forceinline__ uint32_t f2tf(float f){ uint32_t r; asm("cvt.rna.tf32.f32 %0,%1;":"=r"(r):"f"(f)); return r; }
__device__ __forceinline__ uint32_t bf16r(float f){ uint16_t r; asm("cvt.rn.bf16.f32 %0,%1;":"=h"(r):"f"(f)); return (uint32_t)r; }
__device__ __forceinline__ void split_pack(float a, float b, uint32_t &hi, uint32_t &lo){
    uint32_t ha = bf16r(a), hb = bf16r(b);
    float ra = a - __uint_as_float(ha << 16);
    float rb = b - __uint_as_float(hb << 16);
    hi = ha | (hb << 16);
    lo = bf16r(ra) | (bf16r(rb) << 16);
}

__device__ __forceinline__ void mma_tf32(float4 &d, const uint4 &a, const uint2 &b){
    asm volatile("mma.sync.aligned.m16n8k8.row.col.f32.tf32.tf32.f32 "
                 "{%0,%1,%2,%3},{%4,%5,%6,%7},{%8,%9},{%0,%1,%2,%3};"
                 : "+f"(d.x), "+f"(d.y), "+f"(d.z), "+f"(d.w)
                 : "r"(a.x), "r"(a.y), "r"(a.z), "r"(a.w), "r"(b.x), "r"(b.y));
}
__device__ __forceinline__ void mma_bf16(float4 &d, uint32_t a0, uint32_t a1, uint32_t a2, uint32_t a3,
                                         uint32_t b0, uint32_t b1){
    asm volatile("mma.sync.aligned.m16n8k16.row.col.f32.bf16.bf16.f32 "
                 "{%0,%1,%2,%3},{%4,%5,%6,%7},{%8,%9},{%0,%1,%2,%3};"
                 : "+f"(d.x), "+f"(d.y), "+f"(d.z), "+f"(d.w)
                 : "r"(a0), "r"(a1), "r"(a2), "r"(a3), "r"(b0), "r"(b1));
}

__device__ __forceinline__ void cpa16(uint32_t dst, const void* src){
    asm volatile("cp.async.cg.shared.global [%0], [%1], 16;\n" :: "r"(dst), "l"(src));
}
__device__ __forceinline__ void cpa_commit(){ asm volatile("cp.async.commit_group;\n"); }
template<int N> __device__ __forceinline__ void cpa_wait(){ asm volatile("cp.async.wait_group %0;\n"::"n"(N)); }

// ---------------- K0: prep — W split-pack + rq prepack + list init -----------
__global__ __launch_bounds__(256) void k_prep(const float* __restrict__ Wkv,
                                              const float* __restrict__ Wbeta,
                                              const float* __restrict__ Wr,
                                              const float* __restrict__ Wq) {
    const int bid = blockIdx.x, tid = threadIdx.x;
    if (bid < NBK * 192) {
        const int kti = tid >> 2, j = tid & 3;
        int e = bid / 192, n = bid % 192;
        const float* base = (n < 128) ? (Wkv + ((size_t)e * 128 + n) * DD)
                                      : (Wbeta + ((size_t)e * 64 + (n - 128)) * DD);
        const float* src = base + kti * 16 + 2 * j;
        float2 v0 = *(const float2*)src;
        float2 v1 = *(const float2*)(src + 8);
        uint32_t h0, l0, h1, l1;
        split_pack(v0.x, v0.y, h0, l0);
        split_pack(v1.x, v1.y, h1, l1);
        g_wpack[(size_t)bid * 256 + tid] = make_uint4(h0, h1, l0, l1);
    } else if (bid < NBK * 192 + 64) {
        const int kti = bid - NBK * 192;
#pragma unroll
        for (int it = 0; it < 3; it++) {
            int u = tid + it * 256;
            if (u < 640) {
                int nt = u >> 6, rem = u & 63;
                int s = rem >> 5, lane = rem & 31;
                int n = nt * 8 + (lane >> 2);
                const float* wp = (n < 16) ? (Wr + (size_t)n * DD)
                                           : (Wq + (size_t)(n - 16) * DD);
                int k0 = kti * 16 + s * 8 + (lane & 3);
                float e0 = wp[k0], e1 = wp[k0 + 4];
                uint32_t h0 = f2tf(e0), h1 = f2tf(e1);
                uint32_t l0 = f2tf(e0 - __uint_as_float(h0));
                uint32_t l1 = f2tf(e1 - __uint_as_float(h1));
                g_rqpack[kti * 640 + u] = make_uint4(h0, h1, l0, l1);
            }
        }
    } else {
        int i = (bid - (NBK * 192 + 64)) * 256 + tid;
        if (i < NLIST) g_list[i] = 0xFFFFFFFFu;
        if (i < NBK)   g_cursor[i] = i * CAP;
    }
}

// ---------------- K1: router+q GEMM (tf32 3-split, cp.async W) + topk/fill ---
__global__ __launch_bounds__(256) void k_rq_mma(const float* __restrict__ x) {
    __shared__ uint32_t Ah[4*2*32*4], Al[4*2*32*4];
    __shared__ __align__(16) uint4 SB[2][640];     // 20 KB, double-buffered W
    __shared__ float slog[64][20];

    const int tid = threadIdx.x;
    const int row0 = blockIdx.x * 64;
    const int warp = tid >> 5, lane = tid & 31;
    const int wm = warp >> 1, wn = warp & 1;

    float4 acc[5];
#pragma unroll
    for (int j = 0; j < 5; j++) acc[j] = make_float4(0.f, 0.f, 0.f, 0.f);

    const int xrow = tid >> 2, xk0 = (tid & 3) * 4;
    const float* xp = x + (size_t)(row0 + xrow) * DD + xk0;
    const int xs = xk0 >> 3;
    const int xreg = ((xk0 & 4) ? 2 : 0) + (((xrow & 15) >= 8) ? 1 : 0);
    const int xbase = ((((xrow >> 4) * 2 + xs) * 32 + ((xrow & 7) << 2)) << 2) + xreg;

    const uint4* b_src[3];
    uint32_t b_dst[3];
#pragma unroll
    for (int i = 0; i < 3; i++) {
        int u = tid + i * 256;
        if (u < 640) {
            b_src[i] = &g_rqpack[u];
            b_dst[i] = (uint32_t)__cvta_generic_to_shared(&SB[0][u]);
        } else { b_src[i] = nullptr; b_dst[i] = 0; }
    }
    const uint32_t BBUF = 640 * sizeof(uint4);

#pragma unroll
    for (int i = 0; i < 3; i++) if (b_src[i]) cpa16(b_dst[i], b_src[i]);
    cpa_commit();

    for (int kts = 0; kts < NKTI; kts++) {
        const int buf = kts & 1;
        const int kt = kts * 16;
        {
            float4 v = *(const float4*)(xp + kt);
            float vv[4] = {v.x, v.y, v.z, v.w};
#pragma unroll
            for (int j = 0; j < 4; j++) {
                uint32_t h = f2tf(vv[j]);
                Ah[xbase + (j << 2)] = h;
                Al[xbase + (j << 2)] = f2tf(vv[j] - __uint_as_float(h));
            }
        }
        const bool more = (kts + 1 < NKTI);
        if (more) {
            uint32_t bo = (buf ^ 1) * BBUF;
#pragma unroll
            for (int i = 0; i < 3; i++)
                if (b_src[i]) cpa16(b_dst[i] + bo, b_src[i] + (size_t)(kts + 1) * 640);
            cpa_commit();
            cpa_wait<1>();
        } else {
            cpa_wait<0>();
        }
        __syncthreads();
#pragma unroll
        for (int s = 0; s < 2; s++) {
            int aidx = (((wm * 2 + s) * 32 + lane) << 2);
            uint4 ah = *(const uint4*)&Ah[aidx];
            uint4 al = *(const uint4*)&Al[aidx];
#pragma unroll
            for (int ni = 0; ni < 5; ni++) {
                uint4 qb = SB[buf][((wn * 5 + ni) * 2 + s) * 32 + lane];
                uint2 bh = make_uint2(qb.x, qb.y);
                uint2 bl = make_uint2(qb.z, qb.w);
                mma_tf32(acc[ni], ah, bh);
                mma_tf32(acc[ni], ah, bl);
                mma_tf32(acc[ni], al, bh);
            }
        }
        __syncthreads();
    }
    int rloc = wm * 16 + (lane >> 2);
    int r0 = row0 + rloc;
#pragma unroll
    for (int ni = 0; ni < 5; ni++) {
        int c0 = wn * 40 + ni * 8 + ((lane & 3) << 1);
        if (c0 < 16) {
            slog[rloc][c0]     = acc[ni].x; slog[rloc][c0 + 1]     = acc[ni].y;
            slog[rloc + 8][c0] = acc[ni].z; slog[rloc + 8][c0 + 1] = acc[ni].w;
        } else {
            int c = c0 - 16;
            *(float2*)&g_q[(size_t)r0 * 64 + c]       = make_float2(acc[ni].x, acc[ni].y);
            *(float2*)&g_q[(size_t)(r0 + 8) * 64 + c] = make_float2(acc[ni].z, acc[ni].w);
        }
    }
    __syncthreads();
    if (tid < 64) {
        int tok = row0 + tid;
        float lg[16];
#pragma unroll
        for (int c = 0; c < 16; c++) lg[c] = slog[tid][c];
        float v0 = -1e30f, v1 = -1e30f; int i0 = 0, i1 = 0;
#pragma unroll
        for (int c = 0; c < 16; c++) {
            float l = lg[c];
            if (l > v0) { v1 = v0; i1 = i0; v0 = l; i0 = c; }
            else if (l > v1) { v1 = l; i1 = c; }
        }
        float s = 0.0f, w[16];
#pragma unroll
        for (int c = 0; c < 16; c++) { float e = __expf(lg[c] - v0); w[c] = e; s += e; }
        float rs = 1.0f / s;
#pragma unroll
        for (int c = 0; c < 16; c++) g_w[(size_t)tok * 16 + c] = w[c] * rs;
        g_sel[tok * 2 + 0] = i0;
        g_sel[tok * 2 + 1] = i1;
        int p0 = atomicAdd(&g_cursor[i0], 1); g_list[p0] = (unsigned)(tok * 2);
        int p1 = atomicAdd(&g_cursor[i1], 1); g_list[p1] = (unsigned)(tok * 2 + 1);
    }
}

// ---------------- K2: grouped bf16 3-split GEMM (unchanged) ------------------
__global__ __launch_bounds__(256, 2) void k_ggemm(const float* __restrict__ x) {
    __shared__ __align__(16) uint4 SMA[2][4 * 2 * 32];
    __shared__ __align__(16) uint4 SMB[2][24 * 32];
    __shared__ unsigned s_ent[64];

    const int tid = threadIdx.x;
    const int e = blockIdx.x >> 7;
    const int lofs = e * CAP + (blockIdx.x & 127) * 64;
    if (tid < 64) s_ent[tid] = g_list[lofs + tid];
    __syncthreads();
    if (s_ent[0] == 0xFFFFFFFFu) return;

    const int warp = tid >> 5, lane = tid & 31;
    const int wm = warp >> 2, wn = warp & 3;

    const int a_mt = tid >> 6, a_rlow = (tid >> 3) & 7, a_j = tid & 7;
    const int a_lane = a_rlow * 4 + (a_j & 3);
    const int a_reg  = (a_j >= 4) ? 2 : 0;
    const float* a_p0;
    const float* a_p1;
    {
        unsigned e0 = s_ent[a_mt * 16 + a_rlow];
        unsigned e1 = s_ent[a_mt * 16 + a_rlow + 8];
        a_p0 = (e0 != 0xFFFFFFFFu) ? (x + (size_t)(e0 >> 1) * DD + 2 * a_j) : nullptr;
        a_p1 = (e1 != 0xFFFFFFFFu) ? (x + (size_t)(e1 >> 1) * DD + 2 * a_j) : nullptr;
    }
    uint32_t a_hi_addr = (uint32_t)__cvta_generic_to_shared(
        &((uint32_t*)&SMA[0][(a_mt * 2 + 0) * 32 + a_lane])[a_reg]);
    uint32_t a_lo_addr = (uint32_t)__cvta_generic_to_shared(
        &((uint32_t*)&SMA[0][(a_mt * 2 + 1) * 32 + a_lane])[a_reg]);

    const uint4* b_src[3];
    uint32_t b_dst[3];
#pragma unroll
    for (int i = 0; i < 3; i++) {
        int u = tid + i * 256;
        int n = u >> 2, j = u & 3;
        b_src[i] = &g_wpack[((size_t)e * 192 + n) * 256 + j];
        b_dst[i] = (uint32_t)__cvta_generic_to_shared(&SMB[0][(n >> 3) * 32 + (n & 7) * 4 + j]);
    }

    float4 acc[2][6];
#pragma unroll
    for (int i = 0; i < 2; i++)
#pragma unroll
        for (int j = 0; j < 6; j++) acc[i][j] = make_float4(0.f, 0.f, 0.f, 0.f);

    {
        float2 v0 = make_float2(0.f, 0.f), v1 = v0;
        if (a_p0) v0 = *(const float2*)a_p0;
        if (a_p1) v1 = *(const float2*)a_p1;
        uint32_t h0, l0, h1, l1;
        split_pack(v0.x, v0.y, h0, l0);
        split_pack(v1.x, v1.y, h1, l1);
        asm volatile("st.shared.v2.u32 [%0], {%1,%2};" :: "r"(a_hi_addr), "r"(h0), "r"(h1));
        asm volatile("st.shared.v2.u32 [%0], {%1,%2};" :: "r"(a_lo_addr), "r"(l0), "r"(l1));
#pragma unroll
        for (int i = 0; i < 3; i++) cpa16(b_dst[i], b_src[i]);
        cpa_commit();
    }

    const uint32_t ABUF = sizeof(uint4) * 4 * 2 * 32;
    const uint32_t BBUF = sizeof(uint4) * 24 * 32;

    for (int kts = 0; kts < NKTI; kts++) {
        const int buf = kts & 1;
        float2 va0 = make_float2(0.f, 0.f), va1 = va0;
        const bool more = (kts + 1 < NKTI);
        if (more) {
            if (a_p0) va0 = *(const float2*)(a_p0 + (kts + 1) * 16);
            if (a_p1) va1 = *(const float2*)(a_p1 + (kts + 1) * 16);
        }
        cpa_wait<0>();
        __syncthreads();
        if (more) {
            uint32_t bo = (buf ^ 1) * BBUF;
#pragma unroll
            for (int i = 0; i < 3; i++) cpa16(b_dst[i] + bo, b_src[i] + (size_t)(kts + 1) * 4);
            cpa_commit();
        }
        {
            const uint4* A0 = SMA[buf];
            const uint4* B0 = SMB[buf];
            uint4 qa_h[2], qa_l[2];
#pragma unroll
            for (int mi = 0; mi < 2; mi++) {
                int mt = wm * 2 + mi;
                qa_h[mi] = A0[(mt * 2 + 0) * 32 + lane];
                qa_l[mi] = A0[(mt * 2 + 1) * 32 + lane];
            }
#pragma unroll
            for (int ni = 0; ni < 6; ni++) {
                uint4 qb = B0[(wn * 6 + ni) * 32 + lane];
#pragma unroll
                for (int mi = 0; mi < 2; mi++) {
                    float4 &d = acc[mi][ni];
                    mma_bf16(d, qa_h[mi].x, qa_h[mi].y, qa_h[mi].z, qa_h[mi].w, qb.x, qb.y);
                    mma_bf16(d, qa_h[mi].x, qa_h[mi].y, qa_h[mi].z, qa_h[mi].w, qb.z, qb.w);
                    mma_bf16(d, qa_l[mi].x, qa_l[mi].y, qa_l[mi].z, qa_l[mi].w, qb.x, qb.y);
                }
            }
        }
        if (more) {
            uint32_t h0, l0, h1, l1;
            split_pack(va0.x, va0.y, h0, l0);
            split_pack(va1.x, va1.y, h1, l1);
            uint32_t ao = (buf ^ 1) * ABUF;
            asm volatile("st.shared.v2.u32 [%0], {%1,%2};" :: "r"(a_hi_addr + ao), "r"(h0), "r"(h1));
            asm volatile("st.shared.v2.u32 [%0], {%1,%2};" :: "r"(a_lo_addr + ao), "r"(l0), "r"(l1));
        }
    }

    // epilogue: scatter into interleaved (k,v,bp,pad) layout
#pragma unroll
    for (int mi = 0; mi < 2; mi++) {
        int r0 = (wm * 2 + mi) * 16 + (lane >> 2);
        unsigned e0 = s_ent[r0], e1 = s_ent[r0 + 8];
#pragma unroll
        for (int ni = 0; ni < 6; ni++) {
            int c0 = wn * 48 + ni * 8 + ((lane & 3) << 1);
            float va[2] = {acc[mi][ni].x, acc[mi][ni].y};
            float vb[2] = {acc[mi][ni].z, acc[mi][ni].w};
#pragma unroll
            for (int j = 0; j < 2; j++) {
                int cc = c0 + j;
                int ofs = ((cc & 63) << 2) + (cc >> 6);
                if (e0 != 0xFFFFFFFFu) g_selout[(size_t)e0 * 256 + ofs] = va[j];
                if (e1 != 0xFFFFFFFFu) g_selout[(size_t)e1 * 256 + ofs] = vb[j];
            }
        }
    }
}

// ---------------- K3: recurrent scan v5 (R13 verbatim — measured best) -------
// prefetched independent loads (LDG.128 for both slots), pointer marching,
// 1 barrier/step, 8 CTAs/SM.
__global__ __launch_bounds__(64, 8) void k_scan(const float* __restrict__ b_beta,
                                                float* __restrict__ out) {
    const int bc = blockIdx.x;
    const int b = bc >> 4, c = bc & 15;
    const int tid = threadIdx.x;

    float4 S[16];
#pragma unroll
    for (int j = 0; j < 16; j++) S[j] = make_float4(0.f, 0.f, 0.f, 0.f);
    const float bb = b_beta[c * 64 + tid];

    __shared__ __align__(16) float sq[2][64];
    __shared__ __align__(16) float sk[2][64];

    // marching pointers
    const float*  qp   = g_q + (size_t)b * 64 + tid;
    const int2*   selp = (const int2*)g_sel + b;
    const float*  wp   = g_w + (size_t)b * 16 + c;
    const float*  sop  = g_selout + (size_t)b * 512 + tid * 4;
    float*        pp   = g_partial + ((size_t)b * 16 + c) * 64 + tid;

    // prefetch t = 0 (5 independent loads)
    float qv = *qp;
    int2  sel = *selp;
    float wv = *wp;
    float4 f0 = *(const float4*)sop;          // slot0: (k, v, bp, pad)
    float4 f1 = *(const float4*)(sop + 256);  // slot1

    for (int t = 0; t < TT; t++) {
        const int p = t & 1;
        const int slotc = (sel.x == c) ? 0 : ((sel.y == c) ? 1 : -1);
        float kk, vvc, bpc;
        if (slotc == 0) { kk = f0.x; vvc = f0.y; bpc = f0.z; }
        else            { kk = f1.x; vvc = f1.y; bpc = f1.z; }
        const float wvc = wv;
        sq[p][tid] = qv;
        sk[p][tid] = kk;
        __syncthreads();                       // one barrier per step

        // issue t+1 loads (fly under compute)
        if (t + 1 < TT) {
            qp += BB * 64; selp += BB; wp += BB * 16; sop += (size_t)BB * 512;
            qv = *qp;
            sel = *selp;
            wv = *wp;
            f0 = *(const float4*)sop;
            f1 = *(const float4*)(sop + 256);
        }

        if (slotc >= 0) {                      // CTA-uniform
            float k0 = sk[p][tid], k1 = sk[p][tid ^ 32];
            float ps = fmaf(k0, k0, k1 * k1);
#pragma unroll
            for (int o = 16; o; o >>= 1) ps += __shfl_xor_sync(0xffffffffu, ps, o);
            float rn = fast_rcp(sqrtf(ps) + 1e-6f);
            const float4* k4 = (const float4*)sk[p];
            float r0 = 0.f, r1 = 0.f, r2 = 0.f, r3 = 0.f;
#pragma unroll
            for (int j = 0; j < 16; j++) {
                float4 kq = k4[j];
                r0 = fmaf(S[j].x, kq.x, r0);
                r1 = fmaf(S[j].y, kq.y, r1);
                r2 = fmaf(S[j].z, kq.z, r2);
                r3 = fmaf(S[j].w, kq.w, r3);
            }
            float delta = vvc - ((r0 + r1) + (r2 + r3)) * rn;
            float beta = fsig(bpc + bb);
            float sc = delta * rn;
#pragma unroll 8
            for (int j = 0; j < 16; j++) {
                float4 kq = k4[j];
                S[j].x = ftanh(fmaf(beta, S[j].x, sc * kq.x));
                S[j].y = ftanh(fmaf(beta, S[j].y, sc * kq.y));
                S[j].z = ftanh(fmaf(beta, S[j].z, sc * kq.z));
                S[j].w = ftanh(fmaf(beta, S[j].w, sc * kq.w));
            }
        }
        const float4* q4 = (const float4*)sq[p];
        float a0 = 0.f, a1 = 0.f, a2 = 0.f, a3 = 0.f;
#pragma unroll
        for (int j = 0; j < 16; j++) {
            float4 qq = q4[j];
            a0 = fmaf(S[j].x, qq.x, a0);
            a1 = fmaf(S[j].y, qq.y, a1);
            a2 = fmaf(S[j].z, qq.z, a2);
            a3 = fmaf(S[j].w, qq.w, a3);
        }
        float sv = (a0 + a1) + (a2 + a3);
        *pp = wvc * sv * sv * fsig(sv);
        pp += (size_t)BB * NBK * 64;
    }
    float* Sf = out + OUT_OFF;
    size_t base = (((size_t)b * 16 + c) * 64 + tid) * 64;
#pragma unroll
    for (int j = 0; j < 16; j++) *(float4*)&Sf[base + j * 4] = S[j];
}

// ---------------- K4: reduce over blocks -> outputs (float4) -----------------
__global__ void k_reduce(float* __restrict__ out) {
    int idx = blockIdx.x * 256 + threadIdx.x;      // over TOKN*16 float4s
    int tok = idx >> 4, i4 = idx & 15;
    const float4* p = (const float4*)(g_partial + (size_t)tok * 1024) + i4;
    float4 s = make_float4(0.f, 0.f, 0.f, 0.f);
#pragma unroll
    for (int c = 0; c < 16; c++) {
        float4 v = p[c * 16];
        s.x += v.x; s.y += v.y; s.z += v.z; s.w += v.w;
    }
    ((float4*)out)[idx] = s;
}

// ---------------- launch -----------------------------------------------------
extern "C" void kernel_launch(void* const* d_in, const int* in_sizes, int n_in,
                              void* d_out, int out_size) {
    const float* x    = (const float*)d_in[0];
    const float* Wr   = (const float*)d_in[1];
    const float* Wkv  = (const float*)d_in[2];
    const float* Wb   = (const float*)d_in[3];
    const float* bb   = (const float*)d_in[4];
    const float* Wq   = (const float*)d_in[5];
    float* out = (float*)d_out;
    (void)in_sizes; (void)n_in; (void)out_size;

    const int prep_grid = NBK * 192 + 64 + (NLIST + 255) / 256;   // 3648
    k_prep<<<prep_grid, 256>>>(Wkv, Wb, Wr, Wq);
    k_rq_mma<<<TOKN / 64, 256>>>(x);
    k_ggemm<<<NBK * (CAP / 64), 256>>>(x);
    k_scan<<<BB * NBK, 64>>>(bb, out);
    k_reduce<<<(TOKN * 16) / 256, 256>>>(out);
}